// round 1
// baseline (speedup 1.0000x reference)
#include <cuda_runtime.h>

// Problem sizes (fixed by the reference)
#define T_STEPS 512
#define B_SZ    256
#define EMB_D   128
#define HID_D   256
#define OUT_D   64
#define K_TOT   384            // EMB_D + HID_D

// LSTM persistent-kernel config
#define NB      128            // grid blocks (<= 148 SMs -> all co-resident)
#define NT      256            // threads per block
#define N_BG    4              // batch groups   (64 batches each)
#define N_UG    32             // unit groups    (8 hidden units -> 32 gate rows each)
#define BB_CTA  64             // batches per CTA
#define ROWS    32             // gate rows per CTA
#define APITCH  388            // padded activation pitch (floats), 16B aligned, conflict-spread
#define GPITCH  33             // gate-result pitch

typedef unsigned long long u64;

// ---------------- device scratch (allocation-free; __device__ globals) ------
__device__ float g_hbuf[2][B_SZ][HID_D];   // double-buffered hidden state
__device__ float g_last[B_SZ][HID_D];      // h at last valid timestep per batch
__device__ int   g_idx[B_SZ];              // last valid index per batch
__device__ unsigned g_bar_sense;           // grid barrier (zero-init; returns to 0
__device__ unsigned g_bar_count;           //  after 512 barriers -> replay-safe)

// ---------------- f32x2 helpers (PTX-only pattern on sm_103a) ---------------
__device__ __forceinline__ u64 ffma2(u64 a, u64 b, u64 c) {
    u64 d;
    asm("fma.rn.f32x2 %0, %1, %2, %3;" : "=l"(d) : "l"(a), "l"(b), "l"(c));
    return d;
}
__device__ __forceinline__ u64 packdup(float x) {
    u64 d; unsigned u = __float_as_uint(x);
    asm("mov.b64 %0, {%1, %1};" : "=l"(d) : "r"(u));
    return d;
}
__device__ __forceinline__ void unpack2(u64 v, float& lo, float& hi) {
    unsigned a, b;
    asm("mov.b64 {%0, %1}, %2;" : "=r"(a), "=r"(b) : "l"(v));
    lo = __uint_as_float(a); hi = __uint_as_float(b);
}

// ---------------- replay-safe sense-reversal grid barrier -------------------
__device__ __forceinline__ void grid_barrier(unsigned target) {
    __threadfence();
    __syncthreads();
    if (threadIdx.x == 0) {
        unsigned a = atomicAdd(&g_bar_count, 1u);
        if (a == NB - 1) {
            atomicExch(&g_bar_count, 0u);
            __threadfence();
            atomicExch(&g_bar_sense, target);
        } else {
            while (*((volatile unsigned*)&g_bar_sense) != target) { }
        }
    }
    __syncthreads();
    __threadfence();
}

// ---------------- kernel 1: last-valid index = first zero - 1 --------------
__global__ void idx_kernel(const int* __restrict__ x) {
    __shared__ int m;
    int b = blockIdx.x;
    if (threadIdx.x == 0) m = T_STEPS;
    __syncthreads();
    int p = threadIdx.x;
    if (x[b * T_STEPS + p] == 0)       atomicMin(&m, p);
    if (x[b * T_STEPS + p + 256] == 0) atomicMin(&m, p + 256);
    __syncthreads();
    if (threadIdx.x == 0) g_idx[b] = m - 1;
}

// ---------------- kernel 2: persistent LSTM ---------------------------------
__global__ void __launch_bounds__(NT, 1)
lstm_kernel(const int*   __restrict__ x,
            const float* __restrict__ emb,
            const float* __restrict__ W_ih,
            const float* __restrict__ W_hh,
            const float* __restrict__ b_ih,
            const float* __restrict__ b_hh)
{
    extern __shared__ float sm[];
    float* Wt     = sm;                         // [K_TOT][ROWS] k-major transposed weights
    float* As     = Wt + K_TOT * ROWS;          // [BB_CTA][APITCH] activations
    float* Gs     = As + BB_CTA * APITCH;       // [BB_CTA][GPITCH] gate pre-activations
    float* bias_s = Gs + BB_CTA * GPITCH;       // [ROWS]
    float* c_s    = bias_s + ROWS;              // [BB_CTA][8] cell state

    const int tid = threadIdx.x;
    const int bid = blockIdx.x;
    const int ig  = bid >> 5;                   // batch group 0..3
    const int jg  = bid & 31;                   // unit group  0..31
    const int batch0 = ig * BB_CTA;
    const int unit0  = jg * 8;

    // --- one-time init: transpose this CTA's 32 gate rows into smem ---------
    for (int e = tid; e < K_TOT * ROWS; e += NT) {
        int k = e >> 5, lr = e & 31;            // lr = u*4 + gate (gate: i,f,g,o)
        int u = lr >> 2, gate = lr & 3;
        int grow = gate * HID_D + unit0 + u;    // row in [4H] with PyTorch gate order
        float v = (k < EMB_D) ? W_ih[grow * EMB_D + k]
                              : W_hh[grow * HID_D + (k - EMB_D)];
        Wt[k * ROWS + lr] = v;
    }
    if (tid < ROWS) {
        int u = tid >> 2, gate = tid & 3;
        int grow = gate * HID_D + unit0 + u;
        bias_s[tid] = b_ih[grow] + b_hh[grow];
    }
    for (int e = tid; e < BB_CTA * 8; e += NT) c_s[e] = 0.f;
    __syncthreads();

    // thread tile: 2 batches x 4 gate rows (as two f32x2 row-pairs)
    const int rg  = tid & 7;                    // -> rows rg*4 .. rg*4+3 (unit rg)
    const int bbp = tid >> 3;                   // -> batches 2*bbp, 2*bbp+1
    const int bb0 = bbp * 2;
    const int r0  = rg * 4;

    for (int t = 0; t < T_STEPS; t++) {
        // ---- stage activations A = [emb(x[b,t]) | h_t] ----------------------
        const float* hread = &g_hbuf[t & 1][0][0];
        for (int f = tid; f < BB_CTA * (K_TOT / 4); f += NT) {
            int bb = f / (K_TOT / 4);
            int kk = (f % (K_TOT / 4)) * 4;
            int batch = batch0 + bb;
            float4 v;
            if (kk < EMB_D) {
                int tok = x[batch * T_STEPS + t];
                v = *(const float4*)(emb + (long long)tok * EMB_D + kk);
            } else if (t > 0) {
                v = *(const float4*)(hread + batch * HID_D + (kk - EMB_D));
            } else {
                v = make_float4(0.f, 0.f, 0.f, 0.f);
            }
            *(float4*)(As + bb * APITCH + kk) = v;
        }
        __syncthreads();

        // ---- gate GEMM: 8 dots/thread via packed f32x2 FFMA -----------------
        const float* A0 = As + bb0 * APITCH;
        const float* A1 = A0 + APITCH;
        u64 acc00 = 0ull, acc01 = 0ull, acc10 = 0ull, acc11 = 0ull;
        for (int k = 0; k < K_TOT; k += 4) {
            float4 a0 = *(const float4*)(A0 + k);
            float4 a1 = *(const float4*)(A1 + k);
            const float* wk = Wt + k * ROWS + r0;
            #pragma unroll
            for (int s = 0; s < 4; s++) {
                u64 w0 = *(const u64*)(wk + s * ROWS);       // rows r0, r0+1
                u64 w1 = *(const u64*)(wk + s * ROWS + 2);   // rows r0+2, r0+3
                u64 p0 = packdup((&a0.x)[s]);
                u64 p1 = packdup((&a1.x)[s]);
                acc00 = ffma2(p0, w0, acc00);
                acc01 = ffma2(p0, w1, acc01);
                acc10 = ffma2(p1, w0, acc10);
                acc11 = ffma2(p1, w1, acc11);
            }
        }
        {
            float lo, hi;
            unpack2(acc00, lo, hi); Gs[bb0*GPITCH + r0]     = lo; Gs[bb0*GPITCH + r0 + 1] = hi;
            unpack2(acc01, lo, hi); Gs[bb0*GPITCH + r0 + 2] = lo; Gs[bb0*GPITCH + r0 + 3] = hi;
            unpack2(acc10, lo, hi); Gs[(bb0+1)*GPITCH + r0]     = lo; Gs[(bb0+1)*GPITCH + r0 + 1] = hi;
            unpack2(acc11, lo, hi); Gs[(bb0+1)*GPITCH + r0 + 2] = lo; Gs[(bb0+1)*GPITCH + r0 + 3] = hi;
        }
        __syncthreads();

        // ---- elementwise gate combine + h/c update --------------------------
        float* hwrite = &g_hbuf[(t + 1) & 1][0][0];
        #pragma unroll
        for (int rep = 0; rep < 2; rep++) {
            int task = tid + rep * NT;          // 512 tasks = 64 bb x 8 units
            int bb = task >> 3;
            int u  = task & 7;
            const float* gr = Gs + bb * GPITCH + u * 4;
            float gi = gr[0] + bias_s[u*4 + 0];
            float gf = gr[1] + bias_s[u*4 + 1];
            float gg = gr[2] + bias_s[u*4 + 2];
            float go = gr[3] + bias_s[u*4 + 3];
            float ii = 1.f / (1.f + expf(-gi));
            float ff = 1.f / (1.f + expf(-gf));
            float oo = 1.f / (1.f + expf(-go));
            float gt = tanhf(gg);
            float c  = ff * c_s[bb*8 + u] + ii * gt;
            c_s[bb*8 + u] = c;
            float h = oo * tanhf(c);
            int batch = batch0 + bb;
            hwrite[batch * HID_D + unit0 + u] = h;
            if (t == g_idx[batch]) g_last[batch][unit0 + u] = h;
        }
        grid_barrier(1u - (t & 1u));            // 512 barriers: sense returns to 0
    }
}

// ---------------- kernel 3: logits + softmax --------------------------------
__global__ void out_kernel(const float* __restrict__ W_out,
                           const float* __restrict__ b_out,
                           float* __restrict__ out)
{
    int b = blockIdx.x, o = threadIdx.x;
    const float* h = g_last[b];
    const float* w = W_out + o * HID_D;
    float acc = b_out[o];
    for (int k = 0; k < HID_D; k += 4) {
        float4 wv = *(const float4*)(w + k);
        float4 hv = *(const float4*)(h + k);
        acc += wv.x*hv.x + wv.y*hv.y + wv.z*hv.z + wv.w*hv.w;
    }
    __shared__ float red[OUT_D];
    red[o] = acc; __syncthreads();
    for (int s = 32; s > 0; s >>= 1) {
        if (o < s) red[o] = fmaxf(red[o], red[o + s]);
        __syncthreads();
    }
    float m = red[0]; __syncthreads();
    float e = expf(acc - m);
    red[o] = e; __syncthreads();
    for (int s = 32; s > 0; s >>= 1) {
        if (o < s) red[o] += red[o + s];
        __syncthreads();
    }
    out[b * OUT_D + o] = e / red[0];
}

// ---------------- launch ----------------------------------------------------
extern "C" void kernel_launch(void* const* d_in, const int* in_sizes, int n_in,
                              void* d_out, int out_size) {
    const int*   x     = (const int*)  d_in[0];
    const float* emb   = (const float*)d_in[1];
    const float* W_ih  = (const float*)d_in[2];
    const float* W_hh  = (const float*)d_in[3];
    const float* b_ih  = (const float*)d_in[4];
    const float* b_hh  = (const float*)d_in[5];
    const float* W_out = (const float*)d_in[6];
    const float* b_out = (const float*)d_in[7];
    float* out = (float*)d_out;

    idx_kernel<<<B_SZ, 256>>>(x);

    size_t smem = (size_t)(K_TOT*ROWS + BB_CTA*APITCH + BB_CTA*GPITCH + ROWS + BB_CTA*8)
                  * sizeof(float);
    cudaFuncSetAttribute(lstm_kernel, cudaFuncAttributeMaxDynamicSharedMemorySize,
                         (int)smem);
    lstm_kernel<<<NB, NT, smem>>>(x, emb, W_ih, W_hh, b_ih, b_hh);

    out_kernel<<<B_SZ, OUT_D>>>(W_out, b_out, out);
}